// round 13
// baseline (speedup 1.0000x reference)
#include <cuda_runtime.h>

#define NROWS   32768
#define DCOLS   2048
#define C4TOT   (DCOLS / 4)          // 512 float4 columns per row
#define GRID_R  512                  // reduce blocks
#define RPB     (NROWS / GRID_R)     // 64 contiguous rows per block
#define EPS     1e-6f

// Allocation-free scratch; returned to zero by the kernels themselves so
// graph replays see identical initial state.
__device__ float g_u[DCOLS];         // column sum-of-squares accumulators
__device__ float g_s[DCOLS];         // rsqrt scales
__device__ int   g_cnt[C4TOT];       // per-float4-column arrival counters

// Packed f32x2 FMA: acc += v*v (elementwise on the two packed floats).
// SASS FFMA2 — reachable only via PTX (ptxas won't auto-fuse from C++).
#define FMA2_SQ(acc, v) \
    asm("fma.rn.f32x2 %0, %1, %1, %0;" : "+l"(acc) : "l"(v))

// ---------------------------------------------------------------------------
// Pass 1: column sum-of-squares. Block = 512 threads = one FULL row width
// (thread tid owns float4 column tid) -> every row read is one contiguous
// 8 KB stream, identical locality to the roofline scale kernel. Each block
// walks 64 consecutive rows, MLP=4 batched loads, FFMA2 accumulate
// (2 packed FMA per 16 B instead of 4 scalar FMA).
__global__ void __launch_bounds__(512)
reduce2_kernel(const ulonglong2* __restrict__ x) {
    const int tid = threadIdx.x;                    // float4 column 0..511
    const ulonglong2* p =
        x + (size_t)blockIdx.x * RPB * C4TOT + tid;

    unsigned long long a01 = 0ull, a23 = 0ull;      // packed (0.f,0.f)

    #pragma unroll 4
    for (int i = 0; i < RPB; i += 4) {
        ulonglong2 v0 = p[0 * C4TOT];
        ulonglong2 v1 = p[1 * C4TOT];
        ulonglong2 v2 = p[2 * C4TOT];
        ulonglong2 v3 = p[3 * C4TOT];
        p += 4 * C4TOT;
        FMA2_SQ(a01, v0.x); FMA2_SQ(a23, v0.y);
        FMA2_SQ(a01, v1.x); FMA2_SQ(a23, v1.y);
        FMA2_SQ(a01, v2.x); FMA2_SQ(a23, v2.y);
        FMA2_SQ(a01, v3.x); FMA2_SQ(a23, v3.y);
    }

    float f0, f1, f2, f3;
    asm("mov.b64 {%0,%1}, %2;" : "=f"(f0), "=f"(f1) : "l"(a01));
    asm("mov.b64 {%0,%1}, %2;" : "=f"(f2), "=f"(f3) : "l"(a23));

    // Each thread owns scalar columns 4*tid..4*tid+3 within this block:
    // 2048 spread atomics per block, then the proven arrival-counter +
    // atomicExch finalize (one counter guards the thread's 4 columns).
    const int sc = tid * 4;
    atomicAdd(&g_u[sc + 0], f0);
    atomicAdd(&g_u[sc + 1], f1);
    atomicAdd(&g_u[sc + 2], f2);
    atomicAdd(&g_u[sc + 3], f3);
    __threadfence();                                // publish before counting
    if (atomicAdd(&g_cnt[tid], 1) == GRID_R - 1) {  // all blocks published
        float t0 = atomicExch(&g_u[sc + 0], 0.0f);
        float t1 = atomicExch(&g_u[sc + 1], 0.0f);
        float t2 = atomicExch(&g_u[sc + 2], 0.0f);
        float t3 = atomicExch(&g_u[sc + 3], 0.0f);
        g_s[sc + 0] = rsqrtf(t0 + EPS);
        g_s[sc + 1] = rsqrtf(t1 + EPS);
        g_s[sc + 2] = rsqrtf(t2 + EPS);
        g_s[sc + 3] = rsqrtf(t3 + EPS);
        g_cnt[tid] = 0;                             // reset for next replay
    }
}

// ---------------------------------------------------------------------------
// Pass 2: y = x * s[col]. UNCHANGED from R12 — measured 82.6% DRAM /
// 6.55 TB/s combined, at the practical roofline.
__global__ void __launch_bounds__(256)
scaleAll_kernel(const float4* __restrict__ x, float4* __restrict__ y) {
    const unsigned j   = blockIdx.x * 256u + threadIdx.x;
    const int      c4  = j & (C4TOT - 1);                  // 0..511
    const unsigned rq  = j >> 9;                           // row within quarter
    const size_t base  = (size_t)rq * C4TOT + c4;
    const size_t step  = (size_t)(NROWS / 4) * C4TOT;      // 8192-row stride

    const float4 s = ((const float4*)g_s)[c4];             // 8 KB, L1-hot

    float4 v0 = __ldcs(x + base);
    float4 v1 = __ldcs(x + base +     step);
    float4 v2 = __ldcs(x + base + 2 * step);
    float4 v3 = __ldcs(x + base + 3 * step);
    v0.x *= s.x; v0.y *= s.y; v0.z *= s.z; v0.w *= s.w;
    v1.x *= s.x; v1.y *= s.y; v1.z *= s.z; v1.w *= s.w;
    v2.x *= s.x; v2.y *= s.y; v2.z *= s.z; v2.w *= s.w;
    v3.x *= s.x; v3.y *= s.y; v3.z *= s.z; v3.w *= s.w;
    __stcs(y + base,            v0);
    __stcs(y + base +     step, v1);
    __stcs(y + base + 2 * step, v2);
    __stcs(y + base + 3 * step, v3);
}

// ---------------------------------------------------------------------------
extern "C" void kernel_launch(void* const* d_in, const int* in_sizes, int n_in,
                              void* d_out, int out_size) {
    const ulonglong2* xu = (const ulonglong2*)d_in[0];
    const float4*     x  = (const float4*)d_in[0];
    float4*           y  = (float4*)d_out;

    reduce2_kernel<<<GRID_R, 512>>>(xu);

    const unsigned bBlocks = (NROWS / 4) * C4TOT / 256;    // 16384
    scaleAll_kernel<<<bBlocks, 256>>>(x, y);
}

// round 14
// speedup vs baseline: 1.0145x; 1.0145x over previous
#include <cuda_runtime.h>

#define NROWS   32768
#define DCOLS   2048
#define C4TOT   (DCOLS / 4)          // 512 float4 columns per row
#define GRPC4   128                  // float4 cols per column-group
#define NGRP    4                    // column groups
#define BPSM    6                    // reduce blocks per SM (forced by launch_bounds)
#define EPS     1e-6f

// Allocation-free scratch; returned to zero by the kernels themselves so
// graph replays see identical initial state.
__device__ float g_u[DCOLS];         // column sum-of-squares accumulators
__device__ float g_s[DCOLS];         // rsqrt scales
__device__ int   g_cnt[C4TOT];       // per-float4-column arrival counters

// ---------------------------------------------------------------------------
// Pass 1: column sum-of-squares, ONE exactly-even co-resident wave.
// grid = NGRP * nchunk blocks (= 6*nsm), block = 256.
//   blockIdx.x & 3  -> column group (128 float4 cols)
//   blockIdx.x >> 2 -> row chunk (nchunk total)
//   tid & 127       -> float4 col in group;  tid >> 7 -> row sub-worker (2)
// Strided rows, MLP=4 batched loads (R12 body). launch_bounds(256,6) caps
// regs at 42 so all 6 blocks/SM are co-resident: zero wave raggedness.
__global__ void __launch_bounds__(256, BPSM)
reduceAll_kernel(const float4* __restrict__ x, int nchunk) {
    const int tid = threadIdx.x;
    const int c4l = tid & (GRPC4 - 1);                  // 0..127
    const int w   = ((int)(blockIdx.x >> 2) << 1) + (tid >> 7); // row worker
    const int W   = nchunk << 1;                        // workers per column
    const int c4  = (int)(blockIdx.x & 3) * GRPC4 + c4l;
    const size_t coff = (size_t)c4;

    float ax = 0.f, ay = 0.f, az = 0.f, aw = 0.f;
    int r = w;
    for (; r + 3 * W < NROWS; r += 4 * W) {
        float4 v0 = x[(size_t)(r        ) * C4TOT + coff];
        float4 v1 = x[(size_t)(r +     W) * C4TOT + coff];
        float4 v2 = x[(size_t)(r + 2 * W) * C4TOT + coff];
        float4 v3 = x[(size_t)(r + 3 * W) * C4TOT + coff];
        ax = fmaf(v0.x, v0.x, ax); ay = fmaf(v0.y, v0.y, ay);
        az = fmaf(v0.z, v0.z, az); aw = fmaf(v0.w, v0.w, aw);
        ax = fmaf(v1.x, v1.x, ax); ay = fmaf(v1.y, v1.y, ay);
        az = fmaf(v1.z, v1.z, az); aw = fmaf(v1.w, v1.w, aw);
        ax = fmaf(v2.x, v2.x, ax); ay = fmaf(v2.y, v2.y, ay);
        az = fmaf(v2.z, v2.z, az); aw = fmaf(v2.w, v2.w, aw);
        ax = fmaf(v3.x, v3.x, ax); ay = fmaf(v3.y, v3.y, ay);
        az = fmaf(v3.z, v3.z, az); aw = fmaf(v3.w, v3.w, aw);
    }
    for (; r < NROWS; r += W) {
        float4 v = x[(size_t)r * C4TOT + coff];
        ax = fmaf(v.x, v.x, ax); ay = fmaf(v.y, v.y, ay);
        az = fmaf(v.z, v.z, az); aw = fmaf(v.w, v.w, aw);
    }

    // Direct spread atomics (no smem stage): ~933K adds over 2048 addresses.
    const int sc = c4 * 4;
    atomicAdd(&g_u[sc + 0], ax);
    atomicAdd(&g_u[sc + 1], ay);
    atomicAdd(&g_u[sc + 2], az);
    atomicAdd(&g_u[sc + 3], aw);
    __threadfence();                                    // publish before count
    // 2 contributors per block per column -> W total arrivals.
    if (atomicAdd(&g_cnt[c4], 1) == W - 1) {            // all published
        float t0 = atomicExch(&g_u[sc + 0], 0.0f);      // complete sums + reset
        float t1 = atomicExch(&g_u[sc + 1], 0.0f);
        float t2 = atomicExch(&g_u[sc + 2], 0.0f);
        float t3 = atomicExch(&g_u[sc + 3], 0.0f);
        g_s[sc + 0] = rsqrtf(t0 + EPS);
        g_s[sc + 1] = rsqrtf(t1 + EPS);
        g_s[sc + 2] = rsqrtf(t2 + EPS);
        g_s[sc + 3] = rsqrtf(t3 + EPS);
        g_cnt[c4] = 0;                                  // reset for next replay
    }
}

// ---------------------------------------------------------------------------
// Pass 2: y = x * s[col]. UNCHANGED — measured 82.6% DRAM / 6.55 TB/s
// combined, at the practical roofline.
__global__ void __launch_bounds__(256)
scaleAll_kernel(const float4* __restrict__ x, float4* __restrict__ y) {
    const unsigned j   = blockIdx.x * 256u + threadIdx.x;
    const int      c4  = j & (C4TOT - 1);                  // 0..511
    const unsigned rq  = j >> 9;                           // row within quarter
    const size_t base  = (size_t)rq * C4TOT + c4;
    const size_t step  = (size_t)(NROWS / 4) * C4TOT;      // 8192-row stride

    const float4 s = ((const float4*)g_s)[c4];             // 8 KB, L1-hot

    float4 v0 = __ldcs(x + base);
    float4 v1 = __ldcs(x + base +     step);
    float4 v2 = __ldcs(x + base + 2 * step);
    float4 v3 = __ldcs(x + base + 3 * step);
    v0.x *= s.x; v0.y *= s.y; v0.z *= s.z; v0.w *= s.w;
    v1.x *= s.x; v1.y *= s.y; v1.z *= s.z; v1.w *= s.w;
    v2.x *= s.x; v2.y *= s.y; v2.z *= s.z; v2.w *= s.w;
    v3.x *= s.x; v3.y *= s.y; v3.z *= s.z; v3.w *= s.w;
    __stcs(y + base,            v0);
    __stcs(y + base +     step, v1);
    __stcs(y + base + 2 * step, v2);
    __stcs(y + base + 3 * step, v3);
}

// ---------------------------------------------------------------------------
extern "C" void kernel_launch(void* const* d_in, const int* in_sizes, int n_in,
                              void* d_out, int out_size) {
    const float4* x = (const float4*)d_in[0];
    float4*       y = (float4*)d_out;

    static int nsm = 0;
    if (nsm == 0) {
        cudaDeviceProp prop;
        cudaGetDeviceProperties(&prop, 0);
        nsm = prop.multiProcessorCount;                 // 152 on GB300
    }
    const int nchunk = (BPSM * nsm) / NGRP;             // 228 row chunks
    const int aBlocks = NGRP * nchunk;                  // 912 = exactly 6/SM

    reduceAll_kernel<<<aBlocks, 256>>>(x, nchunk);

    const unsigned bBlocks = (NROWS / 4) * C4TOT / 256; // 16384
    scaleAll_kernel<<<bBlocks, 256>>>(x, y);
}

// round 15
// speedup vs baseline: 1.1128x; 1.0969x over previous
#include <cuda_runtime.h>

#define NROWS   32768
#define DCOLS   2048
#define C4TOT   (DCOLS / 4)          // 512 float4 columns per row
#define GRPC4   128                  // float4 cols per column-group
#define NGRP    (C4TOT / GRPC4)      // 4 column-groups
#define GY      304                  // row-chunk blocks per group (2*152)
#define EPS     1e-6f

// Allocation-free scratch (__device__ globals); returned to zero by the
// kernels themselves so graph replays see identical initial state.
__device__ float g_u[DCOLS];         // column sum-of-squares accumulators
__device__ float g_s[DCOLS];         // rsqrt scales
__device__ int   g_cnt[DCOLS];       // per-column arrival counters

// ---------------------------------------------------------------------------
// Pass 1: column sum-of-squares, one launch. IDENTICAL to the R12 kernel
// (best measured reduce: 51.6us) except the x loads are __ldcs — evict-first
// streaming policy, matching the roofline scale kernel. Default (allocating)
// loads are the one policy difference between the 6.85 TB/s scale stream and
// the 5.1 TB/s reduce stream.
__global__ void __launch_bounds__(512)
reduceAll_kernel(const float4* __restrict__ x) {
    const int tid = threadIdx.x;
    const int c4l = tid & (GRPC4 - 1);               // 0..127
    const int w   = ((int)blockIdx.y << 2) + (tid >> 7); // row worker id
    const int W   = GY << 2;                         // 1216 row workers
    const size_t coff = (size_t)blockIdx.x * GRPC4 + c4l;

    float ax = 0.f, ay = 0.f, az = 0.f, aw = 0.f;
    int r = w;
    for (; r + 3 * W < NROWS; r += 4 * W) {
        float4 v0 = __ldcs(&x[(size_t)(r        ) * C4TOT + coff]);
        float4 v1 = __ldcs(&x[(size_t)(r +     W) * C4TOT + coff]);
        float4 v2 = __ldcs(&x[(size_t)(r + 2 * W) * C4TOT + coff]);
        float4 v3 = __ldcs(&x[(size_t)(r + 3 * W) * C4TOT + coff]);
        ax = fmaf(v0.x, v0.x, ax); ay = fmaf(v0.y, v0.y, ay);
        az = fmaf(v0.z, v0.z, az); aw = fmaf(v0.w, v0.w, aw);
        ax = fmaf(v1.x, v1.x, ax); ay = fmaf(v1.y, v1.y, ay);
        az = fmaf(v1.z, v1.z, az); aw = fmaf(v1.w, v1.w, aw);
        ax = fmaf(v2.x, v2.x, ax); ay = fmaf(v2.y, v2.y, ay);
        az = fmaf(v2.z, v2.z, az); aw = fmaf(v2.w, v2.w, aw);
        ax = fmaf(v3.x, v3.x, ax); ay = fmaf(v3.y, v3.y, ay);
        az = fmaf(v3.z, v3.z, aw == aw ? az : az); aw = fmaf(v3.w, v3.w, aw);
    }
    for (; r < NROWS; r += W) {
        float4 v = __ldcs(&x[(size_t)r * C4TOT + coff]);
        ax = fmaf(v.x, v.x, ax); ay = fmaf(v.y, v.y, ay);
        az = fmaf(v.z, v.z, az); aw = fmaf(v.w, v.w, aw);
    }

    // Combine the 4 row-workers per column in shared (unique slots).
    __shared__ float sacc[4][GRPC4 * 4];
    const int rw = tid >> 7;
    sacc[rw][c4l * 4 + 0] = ax;
    sacc[rw][c4l * 4 + 1] = ay;
    sacc[rw][c4l * 4 + 2] = az;
    sacc[rw][c4l * 4 + 3] = aw;
    __syncthreads();

    // 512 threads -> the 512 scalar columns of this group
    const int scol = (int)blockIdx.x * (GRPC4 * 4) + tid;
    float v = sacc[0][tid] + sacc[1][tid] + sacc[2][tid] + sacc[3][tid];
    atomicAdd(&g_u[scol], v);
    __threadfence();                                 // publish before counting
    if (atomicAdd(&g_cnt[scol], 1) == GY - 1) {      // all GY blocks published
        float total = atomicExch(&g_u[scol], 0.0f);  // complete sum + reset
        g_s[scol]   = rsqrtf(total + EPS);
        g_cnt[scol] = 0;                             // reset for next replay
    }
}

// ---------------------------------------------------------------------------
// Pass 2: y = x * s[col]. UNCHANGED — measured 82.6% DRAM / 6.55 TB/s,
// at the practical roofline.
__global__ void __launch_bounds__(256)
scaleAll_kernel(const float4* __restrict__ x, float4* __restrict__ y) {
    const unsigned j   = blockIdx.x * 256u + threadIdx.x;
    const int      c4  = j & (C4TOT - 1);                  // 0..511
    const unsigned rq  = j >> 9;                           // row within quarter
    const size_t base  = (size_t)rq * C4TOT + c4;
    const size_t step  = (size_t)(NROWS / 4) * C4TOT;      // 8192-row stride

    const float4 s = ((const float4*)g_s)[c4];             // 8 KB, L1-hot

    float4 v0 = __ldcs(x + base);
    float4 v1 = __ldcs(x + base +     step);
    float4 v2 = __ldcs(x + base + 2 * step);
    float4 v3 = __ldcs(x + base + 3 * step);
    v0.x *= s.x; v0.y *= s.y; v0.z *= s.z; v0.w *= s.w;
    v1.x *= s.x; v1.y *= s.y; v1.z *= s.z; v1.w *= s.w;
    v2.x *= s.x; v2.y *= s.y; v2.z *= s.z; v2.w *= s.w;
    v3.x *= s.x; v3.y *= s.y; v3.z *= s.z; v3.w *= s.w;
    __stcs(y + base,            v0);
    __stcs(y + base +     step, v1);
    __stcs(y + base + 2 * step, v2);
    __stcs(y + base + 3 * step, v3);
}

// ---------------------------------------------------------------------------
extern "C" void kernel_launch(void* const* d_in, const int* in_sizes, int n_in,
                              void* d_out, int out_size) {
    const float4* x = (const float4*)d_in[0];
    float4*       y = (float4*)d_out;

    dim3 agrid(NGRP, GY);                           // (4, 304)
    reduceAll_kernel<<<agrid, 512>>>(x);

    const unsigned bBlocks = (NROWS / 4) * C4TOT / 256;    // 16384
    scaleAll_kernel<<<bBlocks, 256>>>(x, y);
}

// round 16
// speedup vs baseline: 1.1190x; 1.0056x over previous
#include <cuda_runtime.h>

#define NROWS   32768
#define DCOLS   2048
#define C4TOT   (DCOLS / 4)          // 512 float4 columns per row
#define GRPC4   128                  // float4 cols per column-group
#define NGRP    (C4TOT / GRPC4)      // 4 column-groups
#define GY      152                  // row-chunk blocks per group
#define EPS     1e-6f

// Allocation-free scratch (__device__ globals); returned to zero by the
// kernels themselves so graph replays see identical initial state.
__device__ float g_u[DCOLS];         // column sum-of-squares accumulators
__device__ float g_s[DCOLS];         // rsqrt scales
__device__ int   g_cnt[DCOLS];       // per-column arrival counters

// ---------------------------------------------------------------------------
// Pass 1: column sum-of-squares with MLP=8: 8 independent __ldcs float4
// loads batched per iteration before any consuming FMA. W = GY*4 = 608 row
// workers per column; each worker owns ~54 rows -> ~6.7 full iterations.
__global__ void __launch_bounds__(512)
reduceAll_kernel(const float4* __restrict__ x) {
    const int tid = threadIdx.x;
    const int c4l = tid & (GRPC4 - 1);               // 0..127
    const int w   = ((int)blockIdx.y << 2) + (tid >> 7); // row worker id
    const int W   = GY << 2;                         // 608 row workers
    const size_t coff = (size_t)blockIdx.x * GRPC4 + c4l;
    const float4* __restrict__ xc = x + coff;

    float ax = 0.f, ay = 0.f, az = 0.f, aw = 0.f;
    int r = w;
    for (; r + 7 * W < NROWS; r += 8 * W) {
        float4 v0 = __ldcs(&xc[(size_t)(r        ) * C4TOT]);
        float4 v1 = __ldcs(&xc[(size_t)(r +     W) * C4TOT]);
        float4 v2 = __ldcs(&xc[(size_t)(r + 2 * W) * C4TOT]);
        float4 v3 = __ldcs(&xc[(size_t)(r + 3 * W) * C4TOT]);
        float4 v4 = __ldcs(&xc[(size_t)(r + 4 * W) * C4TOT]);
        float4 v5 = __ldcs(&xc[(size_t)(r + 5 * W) * C4TOT]);
        float4 v6 = __ldcs(&xc[(size_t)(r + 6 * W) * C4TOT]);
        float4 v7 = __ldcs(&xc[(size_t)(r + 7 * W) * C4TOT]);
        ax = fmaf(v0.x, v0.x, ax); ay = fmaf(v0.y, v0.y, ay);
        az = fmaf(v0.z, v0.z, az); aw = fmaf(v0.w, v0.w, aw);
        ax = fmaf(v1.x, v1.x, ax); ay = fmaf(v1.y, v1.y, ay);
        az = fmaf(v1.z, v1.z, az); aw = fmaf(v1.w, v1.w, aw);
        ax = fmaf(v2.x, v2.x, ax); ay = fmaf(v2.y, v2.y, ay);
        az = fmaf(v2.z, v2.z, az); aw = fmaf(v2.w, v2.w, aw);
        ax = fmaf(v3.x, v3.x, ax); ay = fmaf(v3.y, v3.y, ay);
        az = fmaf(v3.z, v3.z, az); aw = fmaf(v3.w, v3.w, aw);
        ax = fmaf(v4.x, v4.x, ax); ay = fmaf(v4.y, v4.y, ay);
        az = fmaf(v4.z, v4.z, az); aw = fmaf(v4.w, v4.w, aw);
        ax = fmaf(v5.x, v5.x, ax); ay = fmaf(v5.y, v5.y, ay);
        az = fmaf(v5.z, v5.z, az); aw = fmaf(v5.w, v5.w, aw);
        ax = fmaf(v6.x, v6.x, ax); ay = fmaf(v6.y, v6.y, ay);
        az = fmaf(v6.z, v6.z, az); aw = fmaf(v6.w, v6.w, aw);
        ax = fmaf(v7.x, v7.x, ax); ay = fmaf(v7.y, v7.y, ay);
        az = fmaf(v7.z, v7.z, az); aw = fmaf(v7.w, v7.w, aw);
    }
    for (; r < NROWS; r += W) {
        float4 v = __ldcs(&xc[(size_t)r * C4TOT]);
        ax = fmaf(v.x, v.x, ax); ay = fmaf(v.y, v.y, ay);
        az = fmaf(v.z, v.z, az); aw = fmaf(v.w, v.w, aw);
    }

    // Combine the 4 row-workers per column in shared (unique slots).
    __shared__ float sacc[4][GRPC4 * 4];
    const int rw = tid >> 7;
    sacc[rw][c4l * 4 + 0] = ax;
    sacc[rw][c4l * 4 + 1] = ay;
    sacc[rw][c4l * 4 + 2] = az;
    sacc[rw][c4l * 4 + 3] = aw;
    __syncthreads();

    // 512 threads -> the 512 scalar columns of this group
    const int scol = (int)blockIdx.x * (GRPC4 * 4) + tid;
    float v = sacc[0][tid] + sacc[1][tid] + sacc[2][tid] + sacc[3][tid];
    atomicAdd(&g_u[scol], v);
    __threadfence();                                 // publish before counting
    if (atomicAdd(&g_cnt[scol], 1) == GY - 1) {      // all GY blocks published
        float total = atomicExch(&g_u[scol], 0.0f);  // complete sum + reset
        g_s[scol]   = rsqrtf(total + EPS);
        g_cnt[scol] = 0;                             // reset for next replay
    }
}

// ---------------------------------------------------------------------------
// Pass 2: y = x * s[col]. UNCHANGED — measured 82.6% DRAM / 6.55 TB/s,
// at the practical roofline.
__global__ void __launch_bounds__(256)
scaleAll_kernel(const float4* __restrict__ x, float4* __restrict__ y) {
    const unsigned j   = blockIdx.x * 256u + threadIdx.x;
    const int      c4  = j & (C4TOT - 1);                  // 0..511
    const unsigned rq  = j >> 9;                           // row within quarter
    const size_t base  = (size_t)rq * C4TOT + c4;
    const size_t step  = (size_t)(NROWS / 4) * C4TOT;      // 8192-row stride

    const float4 s = ((const float4*)g_s)[c4];             // 8 KB, L1-hot

    float4 v0 = __ldcs(x + base);
    float4 v1 = __ldcs(x + base +     step);
    float4 v2 = __ldcs(x + base + 2 * step);
    float4 v3 = __ldcs(x + base + 3 * step);
    v0.x *= s.x; v0.y *= s.y; v0.z *= s.z; v0.w *= s.w;
    v1.x *= s.x; v1.y *= s.y; v1.z *= s.z; v1.w *= s.w;
    v2.x *= s.x; v2.y *= s.y; v2.z *= s.z; v2.w *= s.w;
    v3.x *= s.x; v3.y *= s.y; v3.z *= s.z; v3.w *= s.w;
    __stcs(y + base,            v0);
    __stcs(y + base +     step, v1);
    __stcs(y + base + 2 * step, v2);
    __stcs(y + base + 3 * step, v3);
}

// ---------------------------------------------------------------------------
extern "C" void kernel_launch(void* const* d_in, const int* in_sizes, int n_in,
                              void* d_out, int out_size) {
    const float4* x = (const float4*)d_in[0];
    float4*       y = (float4*)d_out;

    dim3 agrid(NGRP, GY);                           // (4, 152) = 608 blocks
    reduceAll_kernel<<<agrid, 512>>>(x);

    const unsigned bBlocks = (NROWS / 4) * C4TOT / 256;    // 16384
    scaleAll_kernel<<<bBlocks, 256>>>(x, y);
}